// round 6
// baseline (speedup 1.0000x reference)
#include <cuda_runtime.h>
#include <cstdint>
#include <cstddef>

// Problem constants
#define IN_DIM  512
#define OUT_DIM 256
#define NMID    1280
#define NNODES  1792
#define BATCH   16384

#define TBLK 128          // node-panel width
#define NB   (NMID/TBLK)  // 10 panels
#define MT   128          // rows per CTA in panel kernel
#define KC   16           // k-chunk

// Scratch (device globals: allocation-free per harness rules)
__device__ float g_res[(size_t)BATCH * NNODES];    // results buffer [B][1792]
__device__ float g_effW[(size_t)NNODES * NMID];    // weight * connectivity

// ---------------------------------------------------------------------------
// prep: effW = weight * connectivity
// ---------------------------------------------------------------------------
__global__ void prep_kernel(const float* __restrict__ w, const int* __restrict__ conn) {
    int i = blockIdx.x * blockDim.x + threadIdx.x;
    const int tot = NNODES * NMID;
    for (; i < tot; i += gridDim.x * blockDim.x)
        g_effW[i] = w[i] * (float)conn[i];
}

// ---------------------------------------------------------------------------
// init: res[:, :512] = x
// ---------------------------------------------------------------------------
__global__ void init_kernel(const float* __restrict__ x) {
    size_t i = (size_t)blockIdx.x * blockDim.x + threadIdx.x;
    const size_t tot = (size_t)BATCH * IN_DIM;
    const size_t stride = (size_t)gridDim.x * blockDim.x;
    for (; i < tot; i += stride) {
        size_t b = i >> 9;        // /512
        size_t k = i & 511;
        g_res[b * NNODES + k] = x[i];
    }
}

// ---------------------------------------------------------------------------
// Panel kernel: fused GEMM (P = res[:, :K] @ effW[:, panel]) + triangular sweep
//   CTA: 128 rows x 128 cols, 256 threads, thread tile 8x8, f32x2 packed FMA.
// Smem layout (floats):
//   As[16][132] transposed A chunk   (2112)
//   Bs[16][128] W chunk              (2048)
//   P [128][133] panel accum/values  (17024)  pad 133 -> conflict-free col reads
//   Wd[128][128] diagonal W block    (16384)
//   sb[128], se[128]                 (256)
// total = 37824 floats = 151296 bytes
// ---------------------------------------------------------------------------
#define SMEM_FLOATS (16*132 + 16*128 + 128*133 + 128*128 + 256)
#define SMEM_BYTES  (SMEM_FLOATS * 4)

__global__ void __launch_bounds__(256, 1)
panel_kernel(const float* __restrict__ bias, const int* __restrict__ exist, int t) {
    extern __shared__ float smem[];
    float* As = smem;                 // [KC][132]
    float* Bs = As + KC * 132;        // [KC][128]
    float* P  = Bs + KC * 128;        // [128][133]
    float* Wd = P + 128 * 133;        // [128][128]
    float* sb = Wd + 128 * 128;       // [128]
    float* se = sb + 128;             // [128]

    const int c0 = t * TBLK;          // mid-column offset of this panel
    const int K  = IN_DIM + c0;       // prefix dot length (multiple of 16)
    const int rowbase = blockIdx.x * MT;
    const int tid = threadIdx.x;
    const int tx = tid & 15;          // col group 0..15
    const int ty = tid >> 4;          // row group 0..15

    // 8 rows x 8 cols accumulators, packed as 8 x 4 f32x2
    unsigned long long acc[8][4];
#pragma unroll
    for (int i = 0; i < 8; i++)
#pragma unroll
        for (int j = 0; j < 4; j++) acc[i][j] = 0ULL;

    for (int k0 = 0; k0 < K; k0 += KC) {
        // --- load A chunk [128 rows x 16 k] transposed into As[kk][r] ---
#pragma unroll
        for (int l = 0; l < 2; l++) {
            int idx = tid + l * 256;          // 0..511 float4s
            int r   = idx >> 2;               // 0..127
            int kq  = idx & 3;                // 0..3
            float4 v = *(const float4*)&g_res[(size_t)(rowbase + r) * NNODES + k0 + kq * 4];
            As[(kq * 4 + 0) * 132 + r] = v.x;
            As[(kq * 4 + 1) * 132 + r] = v.y;
            As[(kq * 4 + 2) * 132 + r] = v.z;
            As[(kq * 4 + 3) * 132 + r] = v.w;
        }
        // --- load W chunk [16 k x 128 cols] ---
#pragma unroll
        for (int l = 0; l < 2; l++) {
            int idx = tid + l * 256;          // 0..511 float4s
            int kk  = idx >> 5;               // 0..15
            int cq  = idx & 31;               // 0..31
            *(float4*)&Bs[kk * 128 + cq * 4] =
                *(const float4*)&g_effW[(size_t)(k0 + kk) * NMID + c0 + cq * 4];
        }
        __syncthreads();

#pragma unroll
        for (int kk = 0; kk < KC; kk++) {
            unsigned long long bb[4];
            const unsigned long long* bp =
                (const unsigned long long*)&Bs[kk * 128 + tx * 8];
            bb[0] = bp[0]; bb[1] = bp[1]; bb[2] = bp[2]; bb[3] = bp[3];
#pragma unroll
            for (int i = 0; i < 8; i++) {
                float av = As[kk * 132 + ty * 8 + i];
                unsigned int au = __float_as_uint(av);
                unsigned long long ap;
                asm("mov.b64 %0, {%1, %1};" : "=l"(ap) : "r"(au));
#pragma unroll
                for (int j = 0; j < 4; j++)
                    asm("fma.rn.f32x2 %0, %1, %2, %0;"
                        : "+l"(acc[i][j]) : "l"(ap), "l"(bb[j]));
            }
        }
        __syncthreads();
    }

    // --- dump accumulators to P ---
#pragma unroll
    for (int i = 0; i < 8; i++) {
        int r = ty * 8 + i;
#pragma unroll
        for (int j = 0; j < 4; j++) {
            unsigned int lo, hi;
            asm("mov.b64 {%0, %1}, %2;" : "=r"(lo), "=r"(hi) : "l"(acc[i][j]));
            P[r * 133 + tx * 8 + 2 * j]     = __uint_as_float(lo);
            P[r * 133 + tx * 8 + 2 * j + 1] = __uint_as_float(hi);
        }
    }
    // --- load diagonal block Wd[j][i] = effW[512+c0+j][c0+i], bias, exist ---
#pragma unroll
    for (int l = 0; l < 16; l++) {
        int idx = tid + l * 256;              // 0..4095 float4s
        int j  = idx >> 5;
        int cq = idx & 31;
        *(float4*)&Wd[j * 128 + cq * 4] =
            *(const float4*)&g_effW[(size_t)(IN_DIM + c0 + j) * NMID + c0 + cq * 4];
    }
    if (tid < 128) {
        sb[tid] = bias[c0 + tid];
        se[tid] = (float)exist[c0 + tid];
    }
    __syncthreads();

    // --- triangular sweep: one thread per row, 4-way split accumulator ---
    if (tid < 128) {
        float* Pr = &P[(size_t)tid * 133];
        for (int i = 0; i < TBLK; i++) {
            float a0 = Pr[i], a1 = 0.f, a2 = 0.f, a3 = 0.f;
            int j = 0;
            for (; j + 4 <= i; j += 4) {
                a0 += Pr[j]     * Wd[(j)     * 128 + i];
                a1 += Pr[j + 1] * Wd[(j + 1) * 128 + i];
                a2 += Pr[j + 2] * Wd[(j + 2) * 128 + i];
                a3 += Pr[j + 3] * Wd[(j + 3) * 128 + i];
            }
            for (; j < i; j++) a0 += Pr[j] * Wd[j * 128 + i];
            float z = (a0 + a1) + (a2 + a3);
            float v = 1.0f / (1.0f + __expf(-z));   // sigmoid
            v = (v + sb[i]) * se[i];                 // bias AFTER sigmoid, then existence
            Pr[i] = v;
        }
    }
    __syncthreads();

    // --- coalesced write-back of the 128 new columns ---
#pragma unroll
    for (int l = 0; l < 64; l++) {
        int idx = tid + l * 256;                 // 0..16383
        int r = idx >> 7, c = idx & 127;
        g_res[(size_t)(rowbase + r) * NNODES + IN_DIM + c0 + c] = P[r * 133 + c];
    }
}

// ---------------------------------------------------------------------------
// gather output: out = res[:, -256:]
// ---------------------------------------------------------------------------
__global__ void out_kernel(float* __restrict__ out) {
    size_t i = (size_t)blockIdx.x * blockDim.x + threadIdx.x;
    const size_t tot = (size_t)BATCH * OUT_DIM;
    const size_t stride = (size_t)gridDim.x * blockDim.x;
    for (; i < tot; i += stride) {
        size_t b = i >> 8;        // /256
        size_t o = i & 255;
        out[i] = g_res[b * NNODES + (NNODES - OUT_DIM) + o];
    }
}

// ---------------------------------------------------------------------------
// Blocked lower-triangular solve of the NEAT recurrence:
//   10 panels of 128 nodes; per panel: dense GEMM over the known prefix
//   (fp32x2 packed FMA) fused with an in-smem sequential triangular sweep.
extern "C" void kernel_launch(void* const* d_in, const int* in_sizes, int n_in,
                              void* d_out, int out_size) {
    const float* x     = (const float*)d_in[0];   // [16384, 512]
    const float* w     = (const float*)d_in[1];   // [1792, 1280]
    const float* bias  = (const float*)d_in[2];   // [1280]
    const int*   conn  = (const int*)d_in[3];     // [1792, 1280]
    const int*   exist = (const int*)d_in[4];     // [1280]
    float* out = (float*)d_out;                   // [16384, 256]

    cudaFuncSetAttribute(panel_kernel,
                         cudaFuncAttributeMaxDynamicSharedMemorySize, SMEM_BYTES);

    prep_kernel<<<1024, 256>>>(w, conn);
    init_kernel<<<2048, 256>>>(x);
    for (int t = 0; t < NB; t++)
        panel_kernel<<<BATCH / MT, 256, SMEM_BYTES>>>(bias, exist, t);
    out_kernel<<<2048, 256>>>(out);
}

// round 10
// speedup vs baseline: 2.9045x; 2.9045x over previous
#include <cuda_runtime.h>
#include <cuda_bf16.h>
#include <cstdint>
#include <cstddef>

#define IN_DIM  512
#define OUT_DIM 256
#define NMID    1280
#define NNODES  1792
#define BATCH   16384
#define NB      10
#define NKCH    28            // 1792/64 k-chunks
#define NRB     128           // 16384/128 row blocks
#define TILE_E  8192          // bf16 elems per tile (128 rows x 64 k)

// gmem tile images (SW128-swizzled) + fp32 diagonal blocks
__device__ unsigned short g_resT_hi[(size_t)NRB * NKCH * TILE_E];
__device__ unsigned short g_resT_lo[(size_t)NRB * NKCH * TILE_E];
__device__ unsigned short g_wT_hi[(size_t)NB * NKCH * TILE_E];
__device__ unsigned short g_wT_lo[(size_t)NB * NKCH * TILE_E];
__device__ float          g_Wdiag[(size_t)NB * 128 * 128];   // [t][j][i]

// ---------------- helpers ----------------
__device__ __forceinline__ uint32_t sw128(uint32_t b) { return b ^ ((b >> 3) & 0x70); }
__device__ __forceinline__ unsigned short f2bf(float f) {
    return __bfloat16_as_ushort(__float2bfloat16(f));
}
__device__ __forceinline__ float bfbits2f(uint32_t u) { return __uint_as_float(u << 16); }
__device__ __forceinline__ uint32_t smem_u32(const void* p) {
    uint32_t a;
    asm("{ .reg .u64 t; cvta.to.shared.u64 t, %1; cvt.u32.u64 %0, t; }" : "=r"(a) : "l"(p));
    return a;
}
#define MBAR_INIT(a, c) asm volatile("mbarrier.init.shared.b64 [%0], %1;" :: "r"(a), "r"(c) : "memory")
#define MBAR_TX(a, b)   asm volatile("mbarrier.arrive.expect_tx.shared.b64 _, [%0], %1;" :: "r"(a), "r"(b) : "memory")
#define MBAR_WAIT(a, p) do {                                                        \
    asm volatile("{\n\t.reg .pred P1;\n\t"                                          \
        "W_%=:\n\t"                                                                 \
        "mbarrier.try_wait.parity.acquire.cta.shared::cta.b64 P1, [%0], %1, 0x989680;\n\t" \
        "@P1 bra.uni D_%=;\n\t"                                                     \
        "bra.uni W_%=;\n\t"                                                         \
        "D_%=:\n\t}" :: "r"((uint32_t)(a)), "r"((uint32_t)(p)) : "memory");         \
} while (0)

__device__ __forceinline__ void bulk_g2s(uint32_t dst, const void* src, uint32_t bytes, uint32_t mbar) {
    asm volatile("cp.async.bulk.shared::cluster.global.mbarrier::complete_tx::bytes [%0], [%1], %2, [%3];"
                 :: "r"(dst), "l"(src), "r"(bytes), "r"(mbar) : "memory");
}
__device__ __forceinline__ void ldsm4(uint32_t& r0, uint32_t& r1, uint32_t& r2, uint32_t& r3, uint32_t a) {
    asm volatile("ldmatrix.sync.aligned.m8n8.x4.shared.b16 {%0,%1,%2,%3}, [%4];"
                 : "=r"(r0), "=r"(r1), "=r"(r2), "=r"(r3) : "r"(a));
}
__device__ __forceinline__ void mma16816(float* c, const uint32_t* a, uint32_t b0, uint32_t b1) {
    asm volatile("mma.sync.aligned.m16n8k16.row.col.f32.bf16.bf16.f32 "
        "{%0,%1,%2,%3}, {%4,%5,%6,%7}, {%8,%9}, {%0,%1,%2,%3};"
        : "+f"(c[0]), "+f"(c[1]), "+f"(c[2]), "+f"(c[3])
        : "r"(a[0]), "r"(a[1]), "r"(a[2]), "r"(a[3]), "r"(b0), "r"(b1));
}

// ---------------- prep: W^T -> swizzled bf16 hi/lo tiles ----------------
__global__ void prep_w_kernel(const float* __restrict__ w, const int* __restrict__ conn) {
    int idx = blockIdx.x * blockDim.x + threadIdx.x;        // one 4-elem group
    if (idx >= NB * NKCH * 2048) return;
    int r = idx & 127, tk4 = (idx >> 7) & 15, tile = idx >> 11;
    int kc = tile % NKCH, t = tile / NKCH;
    int c = t * 128 + r;
    unsigned short hh[4], ll[4];
#pragma unroll
    for (int q = 0; q < 4; q++) {
        int k = kc * 64 + tk4 * 4 + q;
        float f = w[(size_t)k * NMID + c] * (float)conn[(size_t)k * NMID + c];
        hh[q] = f2bf(f);
        ll[q] = f2bf(f - bfbits2f(hh[q]));
    }
    uint32_t off = (uint32_t)tile * TILE_E + (sw128((uint32_t)(r * 128 + tk4 * 8)) >> 1);
    *(uint2*)&g_wT_hi[off] = make_uint2(hh[0] | ((uint32_t)hh[1] << 16), hh[2] | ((uint32_t)hh[3] << 16));
    *(uint2*)&g_wT_lo[off] = make_uint2(ll[0] | ((uint32_t)ll[1] << 16), ll[2] | ((uint32_t)ll[3] << 16));
}
__global__ void prep_wd_kernel(const float* __restrict__ w, const int* __restrict__ conn) {
    int idx = blockIdx.x * blockDim.x + threadIdx.x;
    if (idx >= NB * 128 * 128) return;
    int i = idx & 127, j = (idx >> 7) & 127, t = idx >> 14;
    size_t src = (size_t)(IN_DIM + t * 128 + j) * NMID + t * 128 + i;
    g_Wdiag[idx] = w[src] * (float)conn[src];
}
// ---------------- init: x -> res tiles (chunks 0..7) ----------------
__global__ void init_x_kernel(const float* __restrict__ x) {
    int idx = blockIdx.x * blockDim.x + threadIdx.x;        // one 4-elem group
    if (idx >= BATCH * 128) return;
    int k4 = idx & 127, b = idx >> 7;
    float4 v = *(const float4*)&x[(size_t)b * IN_DIM + k4 * 4];
    float f[4] = {v.x, v.y, v.z, v.w};
    unsigned short hh[4], ll[4];
#pragma unroll
    for (int q = 0; q < 4; q++) { hh[q] = f2bf(f[q]); ll[q] = f2bf(f[q] - bfbits2f(hh[q])); }
    int rb = b >> 7, tr = b & 127, kc = k4 >> 4, tk4 = k4 & 15;
    uint32_t off = (uint32_t)(rb * NKCH + kc) * TILE_E + (sw128((uint32_t)(tr * 128 + tk4 * 8)) >> 1);
    *(uint2*)&g_resT_hi[off] = make_uint2(hh[0] | ((uint32_t)hh[1] << 16), hh[2] | ((uint32_t)hh[3] << 16));
    *(uint2*)&g_resT_lo[off] = make_uint2(ll[0] | ((uint32_t)ll[1] << 16), ll[2] | ((uint32_t)ll[3] << 16));
}

// ---------------- fused kernel ----------------
// smem: [0,131072) 2 stages of {Ahi,Alo,Bhi,Blo} 16KB; P fp32 [128][133] overlays
//       [131072,196608) Wd fp32 [j][i]; then sbv, sev, 5 mbarriers
#define SM_STAGE 65536
#define SM_WD    131072
#define SM_SBV   196608
#define SM_SEV   197120
#define SM_BARS  197632   // full0 +0, full1 +8, wd +16
#define SMEM_SZ  197696

__device__ __forceinline__ void load_chunk(uint32_t sb32, int rb, int t, int c, int s) {
    uint32_t mbar = sb32 + SM_BARS + s * 8;
    uint32_t stg  = sb32 + s * SM_STAGE;
    MBAR_TX(mbar, 65536);
    size_t a = ((size_t)rb * NKCH + c) * TILE_E;
    size_t b = ((size_t)t  * NKCH + c) * TILE_E;
    bulk_g2s(stg,         &g_resT_hi[a], 16384, mbar);
    bulk_g2s(stg + 16384, &g_resT_lo[a], 16384, mbar);
    bulk_g2s(stg + 32768, &g_wT_hi[b],   16384, mbar);
    bulk_g2s(stg + 49152, &g_wT_lo[b],   16384, mbar);
}

__global__ void __launch_bounds__(256, 1)
fused_kernel(const float* __restrict__ bias, const int* __restrict__ exist,
             float* __restrict__ out) {
    extern __shared__ char smem[];
    const uint32_t sb32 = smem_u32(smem);
    float* P   = (float*)smem;                  // [128][133] overlays stages
    float* Wd  = (float*)(smem + SM_WD);        // [j][i]
    float* sbv = (float*)(smem + SM_SBV);
    float* sev = (float*)(smem + SM_SEV);
    const int tid = threadIdx.x, wid = tid >> 5, lane = tid & 31;
    const int rb = blockIdx.x;
    const int warp_m = wid & 1, warp_n = wid >> 1;   // 2 x 4 warp grid, 64x32 tiles

    if (tid == 0) { for (int i = 0; i < 3; i++) MBAR_INIT(sb32 + SM_BARS + i * 8, 1); }
    __syncthreads();

    int f0 = 0, f1 = 0, fw = 0;   // mbarrier phase ledger (per thread)

    for (int t = 0; t < NB; t++) {
        const int c0 = t * 128, nch = 8 + 2 * t;

        if (tid == 0) {
            asm volatile("fence.proxy.async;" ::: "memory");
            load_chunk(sb32, rb, t, 0, 0);
            load_chunk(sb32, rb, t, 1, 1);
            MBAR_TX(sb32 + SM_BARS + 16, 65536);
            bulk_g2s(sb32 + SM_WD, &g_Wdiag[(size_t)t * 16384], 65536, sb32 + SM_BARS + 16);
        }

        float acc[4][4][4];
#pragma unroll
        for (int mi = 0; mi < 4; mi++)
#pragma unroll
            for (int ni = 0; ni < 4; ni++)
#pragma unroll
                for (int q = 0; q < 4; q++) acc[mi][ni][q] = 0.f;

        for (int c = 0; c < nch; c++) {
            int s = c & 1;
            uint32_t stg = sb32 + s * SM_STAGE;
            if (s == 0) { MBAR_WAIT(sb32 + SM_BARS + 0, f0); f0 ^= 1; }
            else        { MBAR_WAIT(sb32 + SM_BARS + 8, f1); f1 ^= 1; }

#pragma unroll
            for (int ks = 0; ks < 4; ks++) {
                uint32_t ah[4][4], al[4][4];
#pragma unroll
                for (int mi = 0; mi < 4; mi++) {
                    int row = 64 * warp_m + 16 * mi + (lane & 15);
                    uint32_t adr = stg + sw128((uint32_t)(row * 128 + ks * 32 + ((lane >> 4) << 4)));
                    ldsm4(ah[mi][0], ah[mi][1], ah[mi][2], ah[mi][3], adr);
                    ldsm4(al[mi][0], al[mi][1], al[mi][2], al[mi][3], adr + 16384);
                }
#pragma unroll
                for (int p = 0; p < 2; p++) {
                    int brow = 32 * warp_n + p * 16 + (lane & 7) + ((lane >> 4) << 3);
                    uint32_t badr = stg + 32768 +
                        sw128((uint32_t)(brow * 128 + ks * 32 + (((lane >> 3) & 1) << 4)));
                    uint32_t bh[4], bl[4];
                    ldsm4(bh[0], bh[1], bh[2], bh[3], badr);
                    ldsm4(bl[0], bl[1], bl[2], bl[3], badr + 16384);
#pragma unroll
                    for (int mi = 0; mi < 4; mi++)
#pragma unroll
                        for (int q = 0; q < 2; q++) {
                            float* cc = acc[mi][2 * p + q];
                            mma16816(cc, ah[mi], bh[2 * q], bh[2 * q + 1]);
                            mma16816(cc, ah[mi], bl[2 * q], bl[2 * q + 1]);
                            mma16816(cc, al[mi], bh[2 * q], bh[2 * q + 1]);
                        }
                }
            }
            __syncthreads();                       // stage s fully consumed
            if (tid == 0 && c + 2 < nch) load_chunk(sb32, rb, t, c + 2, s);
        }

        // ---- epilogue: accumulators -> P (stages now free) ----
#pragma unroll
        for (int mi = 0; mi < 4; mi++)
#pragma unroll
            for (int ni = 0; ni < 4; ni++) {
                int r0 = 64 * warp_m + 16 * mi + (lane >> 2);
                int cc = 32 * warp_n + 8 * ni + 2 * (lane & 3);
                P[r0 * 133 + cc]           = acc[mi][ni][0];
                P[r0 * 133 + cc + 1]       = acc[mi][ni][1];
                P[(r0 + 8) * 133 + cc]     = acc[mi][ni][2];
                P[(r0 + 8) * 133 + cc + 1] = acc[mi][ni][3];
            }
        if (tid < 128) {
            sbv[tid] = bias[c0 + tid];
            sev[tid] = (float)exist[c0 + tid];
        }
        MBAR_WAIT(sb32 + SM_BARS + 16, fw); fw ^= 1;   // Wd landed
        __syncthreads();

        // ---- sweep: 8 sub-blocks of 16 (dense rank-update + small serial) ----
        for (int s = 0; s < 8; s++) {
            {   // dense: P[r][i] += sum_{j<16s} P[r][j] * Wd[j][i]
                int r = tid & 127, i0 = s * 16 + (tid >> 7) * 8;
                float a[8];
#pragma unroll
                for (int ii = 0; ii < 8; ii++) a[ii] = P[r * 133 + i0 + ii];
                for (int j = 0; j < s * 16; j++) {
                    float pv = P[r * 133 + j];
                    float4 w0 = *(const float4*)&Wd[j * 128 + i0];
                    float4 w1 = *(const float4*)&Wd[j * 128 + i0 + 4];
                    a[0] += pv * w0.x; a[1] += pv * w0.y;
                    a[2] += pv * w0.z; a[3] += pv * w0.w;
                    a[4] += pv * w1.x; a[5] += pv * w1.y;
                    a[6] += pv * w1.z; a[7] += pv * w1.w;
                }
#pragma unroll
                for (int ii = 0; ii < 8; ii++) P[r * 133 + i0 + ii] = a[ii];
            }
            __syncthreads();
            if (tid < 128) {   // serial 16x16 triangle, one thread per batch row
                int r = tid;
#pragma unroll 1
                for (int i = 0; i < 16; i++) {
                    int gi = s * 16 + i;
                    float a = P[r * 133 + gi];
                    for (int j = 0; j < i; j++)
                        a += P[r * 133 + s * 16 + j] * Wd[(s * 16 + j) * 128 + gi];
                    float v = 1.0f / (1.0f + __expf(-a));
                    P[r * 133 + gi] = (v + sbv[gi]) * sev[gi];
                }
            }
            __syncthreads();
        }

        // ---- writeback: bf16 hi/lo tile images for later panels ----
        if (t < 9) {
            for (int half = 0; half < 2; half++) {
                size_t tb = ((size_t)rb * NKCH + 8 + 2 * t + half) * TILE_E;
                for (int idx = tid; idx < 128 * 32; idx += 256) {
                    int r = idx >> 5, kp = (idx & 31) * 2;
                    float v0 = P[r * 133 + half * 64 + kp];
                    float v1 = P[r * 133 + half * 64 + kp + 1];
                    unsigned short h0 = f2bf(v0), h1 = f2bf(v1);
                    unsigned short l0 = f2bf(v0 - bfbits2f(h0));
                    unsigned short l1 = f2bf(v1 - bfbits2f(h1));
                    uint32_t off = sw128((uint32_t)(r * 128 + kp * 2)) >> 1;
                    *(uint32_t*)&g_resT_hi[tb + off] = (uint32_t)h0 | ((uint32_t)h1 << 16);
                    *(uint32_t*)&g_resT_lo[tb + off] = (uint32_t)l0 | ((uint32_t)l1 << 16);
                }
            }
        }
        if (t >= 8) {   // panels 8,9 are the 256 output nodes
            for (int idx = tid; idx < 128 * 128; idx += 256) {
                int r = idx >> 7, c = idx & 127;
                out[((size_t)rb * 128 + r) * OUT_DIM + (t - 8) * 128 + c] = P[r * 133 + c];
            }
        }
        __threadfence();
        __syncthreads();
    }
}

// ---------------------------------------------------------------------------
extern "C" void kernel_launch(void* const* d_in, const int* in_sizes, int n_in,
                              void* d_out, int out_size) {
    const float* x     = (const float*)d_in[0];
    const float* w     = (const float*)d_in[1];
    const float* bias  = (const float*)d_in[2];
    const int*   conn  = (const int*)d_in[3];
    const int*   exist = (const int*)d_in[4];
    float* out = (float*)d_out;

    cudaFuncSetAttribute(fused_kernel, cudaFuncAttributeMaxDynamicSharedMemorySize, SMEM_SZ);

    prep_w_kernel<<<(NB * NKCH * 2048 + 255) / 256, 256>>>(w, conn);
    prep_wd_kernel<<<(NB * 128 * 128 + 255) / 256, 256>>>(w, conn);
    init_x_kernel<<<(BATCH * 128 + 255) / 256, 256>>>(x);
    fused_kernel<<<NRB, 256, SMEM_SZ>>>(bias, exist, out);
}

// round 11
// speedup vs baseline: 3.4573x; 1.1904x over previous
#include <cuda_runtime.h>
#include <cuda_bf16.h>
#include <cstdint>
#include <cstddef>

#define IN_DIM  512
#define OUT_DIM 256
#define NMID    1280
#define NNODES  1792
#define BATCH   16384
#define NB      10
#define NKCH    28            // 1792/64 k-chunks
#define NRB     128           // 16384/128 row blocks
#define TILE_E  8192          // bf16 elems per tile (128 rows x 64 k)

// gmem tile images (SW128-swizzled) + fp32 diagonal blocks
__device__ unsigned short g_resT_hi[(size_t)NRB * NKCH * TILE_E];
__device__ unsigned short g_resT_lo[(size_t)NRB * NKCH * TILE_E];
__device__ unsigned short g_wT_hi[(size_t)NB * NKCH * TILE_E];
__device__ unsigned short g_wT_lo[(size_t)NB * NKCH * TILE_E];
__device__ float          g_Wdiag[(size_t)NB * 128 * 128];   // [t][j][i]

// ---------------- helpers ----------------
__device__ __forceinline__ uint32_t sw128(uint32_t b) { return b ^ ((b >> 3) & 0x70); }
__device__ __forceinline__ unsigned short f2bf(float f) {
    return __bfloat16_as_ushort(__float2bfloat16(f));
}
__device__ __forceinline__ float bfbits2f(uint32_t u) { return __uint_as_float(u << 16); }
__device__ __forceinline__ uint32_t smem_u32(const void* p) {
    uint32_t a;
    asm("{ .reg .u64 t; cvta.to.shared.u64 t, %1; cvt.u32.u64 %0, t; }" : "=r"(a) : "l"(p));
    return a;
}
#define MBAR_INIT(a, c) asm volatile("mbarrier.init.shared.b64 [%0], %1;" :: "r"(a), "r"(c) : "memory")
#define MBAR_TX(a, b)   asm volatile("mbarrier.arrive.expect_tx.shared.b64 _, [%0], %1;" :: "r"(a), "r"(b) : "memory")
#define MBAR_WAIT(a, p) do {                                                        \
    asm volatile("{\n\t.reg .pred P1;\n\t"                                          \
        "W_%=:\n\t"                                                                 \
        "mbarrier.try_wait.parity.acquire.cta.shared::cta.b64 P1, [%0], %1, 0x989680;\n\t" \
        "@P1 bra.uni D_%=;\n\t"                                                     \
        "bra.uni W_%=;\n\t"                                                         \
        "D_%=:\n\t}" :: "r"((uint32_t)(a)), "r"((uint32_t)(p)) : "memory");         \
} while (0)

__device__ __forceinline__ void bulk_g2s(uint32_t dst, const void* src, uint32_t bytes, uint32_t mbar) {
    asm volatile("cp.async.bulk.shared::cluster.global.mbarrier::complete_tx::bytes [%0], [%1], %2, [%3];"
                 :: "r"(dst), "l"(src), "r"(bytes), "r"(mbar) : "memory");
}
__device__ __forceinline__ void ldsm4(uint32_t& r0, uint32_t& r1, uint32_t& r2, uint32_t& r3, uint32_t a) {
    asm volatile("ldmatrix.sync.aligned.m8n8.x4.shared.b16 {%0,%1,%2,%3}, [%4];"
                 : "=r"(r0), "=r"(r1), "=r"(r2), "=r"(r3) : "r"(a));
}
__device__ __forceinline__ void mma16816(float* c, const uint32_t* a, uint32_t b0, uint32_t b1) {
    asm volatile("mma.sync.aligned.m16n8k16.row.col.f32.bf16.bf16.f32 "
        "{%0,%1,%2,%3}, {%4,%5,%6,%7}, {%8,%9}, {%0,%1,%2,%3};"
        : "+f"(c[0]), "+f"(c[1]), "+f"(c[2]), "+f"(c[3])
        : "r"(a[0]), "r"(a[1]), "r"(a[2]), "r"(a[3]), "r"(b0), "r"(b1));
}

// ---------------- prep: W^T -> swizzled bf16 hi/lo tiles ----------------
__global__ void prep_w_kernel(const float* __restrict__ w, const int* __restrict__ conn) {
    int idx = blockIdx.x * blockDim.x + threadIdx.x;        // one 4-elem group
    if (idx >= NB * NKCH * 2048) return;
    int r = idx & 127, tk4 = (idx >> 7) & 15, tile = idx >> 11;
    int kc = tile % NKCH, t = tile / NKCH;
    int c = t * 128 + r;
    unsigned short hh[4], ll[4];
#pragma unroll
    for (int q = 0; q < 4; q++) {
        int k = kc * 64 + tk4 * 4 + q;
        float f = w[(size_t)k * NMID + c] * (float)conn[(size_t)k * NMID + c];
        hh[q] = f2bf(f);
        ll[q] = f2bf(f - bfbits2f(hh[q]));
    }
    uint32_t off = (uint32_t)tile * TILE_E + (sw128((uint32_t)(r * 128 + tk4 * 8)) >> 1);
    *(uint2*)&g_wT_hi[off] = make_uint2(hh[0] | ((uint32_t)hh[1] << 16), hh[2] | ((uint32_t)hh[3] << 16));
    *(uint2*)&g_wT_lo[off] = make_uint2(ll[0] | ((uint32_t)ll[1] << 16), ll[2] | ((uint32_t)ll[3] << 16));
}
__global__ void prep_wd_kernel(const float* __restrict__ w, const int* __restrict__ conn) {
    int idx = blockIdx.x * blockDim.x + threadIdx.x;
    if (idx >= NB * 128 * 128) return;
    int i = idx & 127, j = (idx >> 7) & 127, t = idx >> 14;
    size_t src = (size_t)(IN_DIM + t * 128 + j) * NMID + t * 128 + i;
    g_Wdiag[idx] = w[src] * (float)conn[src];
}
// ---------------- init: x -> res tiles (chunks 0..7) ----------------
__global__ void init_x_kernel(const float* __restrict__ x) {
    int idx = blockIdx.x * blockDim.x + threadIdx.x;        // one 4-elem group
    if (idx >= BATCH * 128) return;
    int k4 = idx & 127, b = idx >> 7;
    float4 v = *(const float4*)&x[(size_t)b * IN_DIM + k4 * 4];
    float f[4] = {v.x, v.y, v.z, v.w};
    unsigned short hh[4], ll[4];
#pragma unroll
    for (int q = 0; q < 4; q++) { hh[q] = f2bf(f[q]); ll[q] = f2bf(f[q] - bfbits2f(hh[q])); }
    int rb = b >> 7, tr = b & 127, kc = k4 >> 4, tk4 = k4 & 15;
    uint32_t off = (uint32_t)(rb * NKCH + kc) * TILE_E + (sw128((uint32_t)(tr * 128 + tk4 * 8)) >> 1);
    *(uint2*)&g_resT_hi[off] = make_uint2(hh[0] | ((uint32_t)hh[1] << 16), hh[2] | ((uint32_t)hh[3] << 16));
    *(uint2*)&g_resT_lo[off] = make_uint2(ll[0] | ((uint32_t)ll[1] << 16), ll[2] | ((uint32_t)ll[3] << 16));
}

// ---------------- fused kernel ----------------
// smem: [0,131072) 2 stages of {Ahi,Alo,Bhi,Blo} 16KB; P fp32 [128][133] overlays
//       [131072,196608) Wd fp32 [j][i]; then sbv, sev, mbarriers
#define SM_STAGE 65536
#define SM_WD    131072
#define SM_SBV   196608
#define SM_SEV   197120
#define SM_BARS  197632   // full0 +0, full1 +8, wd +16
#define SMEM_SZ  197696

__device__ __forceinline__ void load_chunk(uint32_t sb32, int rb, int t, int c, int s) {
    uint32_t mbar = sb32 + SM_BARS + s * 8;
    uint32_t stg  = sb32 + s * SM_STAGE;
    MBAR_TX(mbar, 65536);
    size_t a = ((size_t)rb * NKCH + c) * TILE_E;
    size_t b = ((size_t)t  * NKCH + c) * TILE_E;
    bulk_g2s(stg,         &g_resT_hi[a], 16384, mbar);
    bulk_g2s(stg + 16384, &g_resT_lo[a], 16384, mbar);
    bulk_g2s(stg + 32768, &g_wT_hi[b],   16384, mbar);
    bulk_g2s(stg + 49152, &g_wT_lo[b],   16384, mbar);
}

__global__ void __launch_bounds__(256, 1)
fused_kernel(const float* __restrict__ bias, const int* __restrict__ exist,
             float* __restrict__ out) {
    extern __shared__ char smem[];
    const uint32_t sb32 = smem_u32(smem);
    float* P   = (float*)smem;                  // [128][133] overlays stages
    float* Wd  = (float*)(smem + SM_WD);        // [j][i]
    float* sbv = (float*)(smem + SM_SBV);
    float* sev = (float*)(smem + SM_SEV);
    const int tid = threadIdx.x, wid = tid >> 5, lane = tid & 31;
    const int rb = blockIdx.x;
    const int warp_m = wid & 1, warp_n = wid >> 1;   // 2 x 4 warp grid, 64x32 tiles

    if (tid == 0) { for (int i = 0; i < 3; i++) MBAR_INIT(sb32 + SM_BARS + i * 8, 1); }
    __syncthreads();

    int f0 = 0, f1 = 0, fw = 0;   // mbarrier phase ledger (per thread)

    for (int t = 0; t < NB; t++) {
        const int c0 = t * 128, nch = 8 + 2 * t;

        if (tid == 0) {
            asm volatile("fence.proxy.async;" ::: "memory");
            load_chunk(sb32, rb, t, 0, 0);
            load_chunk(sb32, rb, t, 1, 1);
            MBAR_TX(sb32 + SM_BARS + 16, 65536);
            bulk_g2s(sb32 + SM_WD, &g_Wdiag[(size_t)t * 16384], 65536, sb32 + SM_BARS + 16);
        }

        float acc[4][4][4];
#pragma unroll
        for (int mi = 0; mi < 4; mi++)
#pragma unroll
            for (int ni = 0; ni < 4; ni++)
#pragma unroll
                for (int q = 0; q < 4; q++) acc[mi][ni][q] = 0.f;

        for (int c = 0; c < nch; c++) {
            int s = c & 1;
            uint32_t stg = sb32 + s * SM_STAGE;
            if (s == 0) { MBAR_WAIT(sb32 + SM_BARS + 0, f0); f0 ^= 1; }
            else        { MBAR_WAIT(sb32 + SM_BARS + 8, f1); f1 ^= 1; }

#pragma unroll
            for (int ks = 0; ks < 4; ks++) {
                // ---- load ALL fragments for this k-step first ----
                uint32_t ah[4][4], al[4][4], bh[2][4], bl[2][4];
#pragma unroll
                for (int mi = 0; mi < 4; mi++) {
                    int row = 64 * warp_m + 16 * mi + (lane & 15);
                    uint32_t adr = stg + sw128((uint32_t)(row * 128 + ks * 32 + ((lane >> 4) << 4)));
                    ldsm4(ah[mi][0], ah[mi][1], ah[mi][2], ah[mi][3], adr);
                    ldsm4(al[mi][0], al[mi][1], al[mi][2], al[mi][3], adr + 16384);
                }
#pragma unroll
                for (int p = 0; p < 2; p++) {
                    int brow = 32 * warp_n + p * 16 + (lane & 7) + ((lane >> 4) << 3);
                    uint32_t badr = stg + 32768 +
                        sw128((uint32_t)(brow * 128 + ks * 32 + (((lane >> 3) & 1) << 4)));
                    ldsm4(bh[p][0], bh[p][1], bh[p][2], bh[p][3], badr);
                    ldsm4(bl[p][0], bl[p][1], bl[p][2], bl[p][3], badr + 16384);
                }
                // ---- term-major MMA order: same-acc reuse distance = 16 ----
#pragma unroll
                for (int mi = 0; mi < 4; mi++)
#pragma unroll
                    for (int p = 0; p < 2; p++)
#pragma unroll
                        for (int q = 0; q < 2; q++)
                            mma16816(acc[mi][2 * p + q], ah[mi], bh[p][2 * q], bh[p][2 * q + 1]);
#pragma unroll
                for (int mi = 0; mi < 4; mi++)
#pragma unroll
                    for (int p = 0; p < 2; p++)
#pragma unroll
                        for (int q = 0; q < 2; q++)
                            mma16816(acc[mi][2 * p + q], al[mi], bh[p][2 * q], bh[p][2 * q + 1]);
#pragma unroll
                for (int mi = 0; mi < 4; mi++)
#pragma unroll
                    for (int p = 0; p < 2; p++)
#pragma unroll
                        for (int q = 0; q < 2; q++)
                            mma16816(acc[mi][2 * p + q], ah[mi], bl[p][2 * q], bl[p][2 * q + 1]);
            }
            __syncthreads();                       // stage s fully consumed
            if (tid == 0 && c + 2 < nch) load_chunk(sb32, rb, t, c + 2, s);
        }

        // ---- epilogue: accumulators -> P (stages now free) ----
#pragma unroll
        for (int mi = 0; mi < 4; mi++)
#pragma unroll
            for (int ni = 0; ni < 4; ni++) {
                int r0 = 64 * warp_m + 16 * mi + (lane >> 2);
                int cc = 32 * warp_n + 8 * ni + 2 * (lane & 3);
                P[r0 * 133 + cc]           = acc[mi][ni][0];
                P[r0 * 133 + cc + 1]       = acc[mi][ni][1];
                P[(r0 + 8) * 133 + cc]     = acc[mi][ni][2];
                P[(r0 + 8) * 133 + cc + 1] = acc[mi][ni][3];
            }
        if (tid < 128) {
            sbv[tid] = bias[c0 + tid];
            sev[tid] = (float)exist[c0 + tid];
        }
        MBAR_WAIT(sb32 + SM_BARS + 16, fw); fw ^= 1;   // Wd landed
        __syncthreads();

        // ---- sweep: 8 sub-blocks of 16 (dense rank-update + register triangle) ----
        for (int s = 0; s < 8; s++) {
            {   // dense: P[r][i] += sum_{j<16s} P[r][j] * Wd[j][i]
                int r = tid & 127, i0 = s * 16 + (tid >> 7) * 8;
                float a[8];
#pragma unroll
                for (int ii = 0; ii < 8; ii++) a[ii] = P[r * 133 + i0 + ii];
                for (int j = 0; j < s * 16; j++) {
                    float pv = P[r * 133 + j];
                    float4 w0 = *(const float4*)&Wd[j * 128 + i0];
                    float4 w1 = *(const float4*)&Wd[j * 128 + i0 + 4];
                    a[0] += pv * w0.x; a[1] += pv * w0.y;
                    a[2] += pv * w0.z; a[3] += pv * w0.w;
                    a[4] += pv * w1.x; a[5] += pv * w1.y;
                    a[6] += pv * w1.z; a[7] += pv * w1.w;
                }
#pragma unroll
                for (int ii = 0; ii < 8; ii++) P[r * 133 + i0 + ii] = a[ii];
            }
            __syncthreads();
            if (tid < 128) {   // serial 16x16 triangle: values live in registers
                float* Pr = &P[(size_t)tid * 133 + s * 16];
                const float* Wb = &Wd[(s * 16) * 128 + s * 16];
                float pv[16];
#pragma unroll
                for (int i = 0; i < 16; i++) {
                    float a = Pr[i];
#pragma unroll
                    for (int j = 0; j < i; j++)
                        a += pv[j] * Wb[j * 128 + i];     // Wb: warp-uniform broadcast
                    float v = 1.0f / (1.0f + __expf(-a));
                    int gi = s * 16 + i;
                    pv[i] = (v + sbv[gi]) * sev[gi];
                    Pr[i] = pv[i];
                }
            }
            __syncthreads();
        }

        // ---- writeback: bf16 hi/lo tile images for later panels ----
        if (t < 9) {
            for (int half = 0; half < 2; half++) {
                size_t tb = ((size_t)rb * NKCH + 8 + 2 * t + half) * TILE_E;
                for (int idx = tid; idx < 128 * 32; idx += 256) {
                    int r = idx >> 5, kp = (idx & 31) * 2;
                    float v0 = P[r * 133 + half * 64 + kp];
                    float v1 = P[r * 133 + half * 64 + kp + 1];
                    unsigned short h0 = f2bf(v0), h1 = f2bf(v1);
                    unsigned short l0 = f2bf(v0 - bfbits2f(h0));
                    unsigned short l1 = f2bf(v1 - bfbits2f(h1));
                    uint32_t off = sw128((uint32_t)(r * 128 + kp * 2)) >> 1;
                    *(uint32_t*)&g_resT_hi[tb + off] = (uint32_t)h0 | ((uint32_t)h1 << 16);
                    *(uint32_t*)&g_resT_lo[tb + off] = (uint32_t)l0 | ((uint32_t)l1 << 16);
                }
            }
        }
        if (t >= 8) {   // panels 8,9 are the 256 output nodes
            for (int idx = tid; idx < 128 * 128; idx += 256) {
                int r = idx >> 7, c = idx & 127;
                out[((size_t)rb * 128 + r) * OUT_DIM + (t - 8) * 128 + c] = P[r * 133 + c];
            }
        }
        __threadfence();
        __syncthreads();
    }
}

// ---------------------------------------------------------------------------
extern "C" void kernel_launch(void* const* d_in, const int* in_sizes, int n_in,
                              void* d_out, int out_size) {
    const float* x     = (const float*)d_in[0];
    const float* w     = (const float*)d_in[1];
    const float* bias  = (const float*)d_in[2];
    const int*   conn  = (const int*)d_in[3];
    const int*   exist = (const int*)d_in[4];
    float* out = (float*)d_out;

    cudaFuncSetAttribute(fused_kernel, cudaFuncAttributeMaxDynamicSharedMemorySize, SMEM_SZ);

    prep_w_kernel<<<(NB * NKCH * 2048 + 255) / 256, 256>>>(w, conn);
    prep_wd_kernel<<<(NB * 128 * 128 + 255) / 256, 256>>>(w, conn);
    init_x_kernel<<<(BATCH * 128 + 255) / 256, 256>>>(x);
    fused_kernel<<<NRB, 256, SMEM_SZ>>>(bias, exist, out);
}